// round 14
// baseline (speedup 1.0000x reference)
#include <cuda_runtime.h>

// B3-spline undecimated wavelet transform (a trous), 3 levels, fully fused.
// x: (8, 1024, 1024) f32 -> out: (8, 4, 1024, 1024) f32 = [w1, w2, w3, c3]
//
// R14 = R13 + shuffle-based W windows on levels 2/3: each thread loads only
// its own aligned float4 of Q; neighbor float4s come from adjacent lanes via
// __shfl (adjacent lanes = adjacent column groups in the same row). Row/warp
// edge lanes fall back to predicated direct LDS. Cuts ~21% of smem crossbar
// traffic. Level-1 stays gmem-fed (H1 from gmem, W1 prev from gmem).

#define IMG   1024
#define TS    64
#define HL    14
#define S     (TS + 2*HL)   // 92
#define SP    96            // row stride (16B-aligned rows)
#define NTHR  640
#define SHIFT 2             // P phys col = logical col + SHIFT

#define SMEM_FLOATS (2 * S * SP + 8)
#define SMEM_BYTES  (SMEM_FLOATS * sizeof(float))   // 70688 B

__device__ __forceinline__ int reflect_idx(int g) {
    if (g < 0) g = -g;
    if (g >= IMG) g = 2 * IMG - 2 - g;
    return g;
}

__device__ __forceinline__ float4 f4_add(float4 a, float4 b) {
    return make_float4(a.x + b.x, a.y + b.y, a.z + b.z, a.w + b.w);
}

__device__ __forceinline__ float4 shfl_up_f4(float4 v, int delta) {
    float4 r;
    r.x = __shfl_up_sync(0xffffffffu, v.x, delta);
    r.y = __shfl_up_sync(0xffffffffu, v.y, delta);
    r.z = __shfl_up_sync(0xffffffffu, v.z, delta);
    r.w = __shfl_up_sync(0xffffffffu, v.w, delta);
    return r;
}

__device__ __forceinline__ float4 shfl_dn_f4(float4 v, int delta) {
    float4 r;
    r.x = __shfl_down_sync(0xffffffffu, v.x, delta);
    r.y = __shfl_down_sync(0xffffffffu, v.y, delta);
    r.z = __shfl_down_sync(0xffffffffu, v.z, delta);
    r.w = __shfl_down_sync(0xffffffffu, v.w, delta);
    return r;
}

// ---- H1: level-1 vertical conv, gmem -> Q (qs=0). rows [2,90), cols [0,92).
template<bool REFL>
__device__ __forceinline__ void h1_pass(const float* __restrict__ xb,
                                        float* __restrict__ Q,
                                        int ty0, int tx0) {
    const float w0 = 0.0625f, w1 = 0.25f, w2 = 0.375f;
    constexpr int strips = 11, cols = 92;
    for (int idx = threadIdx.x; idx < strips * cols; idx += NTHR) {
        int x  = idx % cols;
        int t  = idx / cols;
        int y0 = 2 + 8 * t;
        float v[12];
        if (REFL) {
            int gx = reflect_idx(tx0 + x - HL);
#pragma unroll
            for (int i = 0; i < 12; i++) {
                int gy = reflect_idx(ty0 + y0 + i - 2 - HL);
                v[i] = xb[gy * IMG + gx];
            }
        } else {
            const float* src = xb + (size_t)(ty0 + y0 - 2 - HL) * IMG
                                  + (tx0 + x - HL);
#pragma unroll
            for (int i = 0; i < 12; i++) v[i] = src[(size_t)i * IMG];
        }
#pragma unroll
        for (int i = 0; i < 8; i++) {
            Q[(y0 + i) * SP + x] = w2 * v[2 + i]
                                 + w1 * (v[1 + i] + v[3 + i])
                                 + w0 * (v[i] + v[4 + i]);
        }
    }
}

// ---- W1: level-1 horizontal conv, Q(qs=0) -> P (c1), emit w1 = x - c1.
__device__ __forceinline__ void w1_pass(float* __restrict__ P,
                                        const float* __restrict__ Q,
                                        const float* __restrict__ xb,
                                        float* __restrict__ wch,
                                        int ty0, int tx0) {
    const float w0 = 0.0625f, w1 = 0.25f, w2 = 0.375f;
    constexpr int n2 = 88, xg = 22;
    for (int idx = threadIdx.x; idx < n2 * xg; idx += NTHR) {
        int g  = idx % xg;
        int y  = 2 + idx / xg;
        int x0 = 2 + 4 * g;                 // logical
        int qw = y * SP + 4 * g;            // window start (logical x0-2, qs=0)
        float v[8];
        float4 t0 = *reinterpret_cast<const float4*>(&Q[qw]);
        float4 t1 = *reinterpret_cast<const float4*>(&Q[qw + 4]);
        v[0]=t0.x; v[1]=t0.y; v[2]=t0.z; v[3]=t0.w;
        v[4]=t1.x; v[5]=t1.y; v[6]=t1.z; v[7]=t1.w;
        float c0 = w2*v[2] + w1*(v[1]+v[3]) + w0*(v[0]+v[4]);
        float c1 = w2*v[3] + w1*(v[2]+v[4]) + w0*(v[1]+v[5]);
        float c2 = w2*v[4] + w1*(v[3]+v[5]) + w0*(v[2]+v[6]);
        float c3 = w2*v[5] + w1*(v[4]+v[6]) + w0*(v[3]+v[7]);
        int op = y * SP + x0 + SHIFT;
        *reinterpret_cast<float4*>(&P[op]) = make_float4(c0, c1, c2, c3);
        if (y >= HL && y < S - HL && x0 >= HL && x0 < S - HL) {
            int gy = ty0 + y - HL;
            int gx = tx0 + x0 - HL;
            float4 prev = *reinterpret_cast<const float4*>(&xb[(size_t)gy * IMG + gx]);
            *reinterpret_cast<float4*>(&wch[gy * IMG + gx]) =
                make_float4(prev.x - c0, prev.y - c1, prev.z - c2, prev.w - c3);
        }
    }
}

// ---- generic level (2, 3): H then shuffle-W, Q at qs=SHIFT ----
template<int d, int h, int a, bool LAST>
__device__ __forceinline__ void do_level(float* __restrict__ P,
                                         float* __restrict__ Q,
                                         float* __restrict__ wch,
                                         float* __restrict__ cch,
                                         int ty0, int tx0) {
    const float w0 = 0.0625f, w1 = 0.25f, w2 = 0.375f;

    // H-conv (vertical): P -> Q. rows [a, S-a), cols [h, S-h). 8-row strips.
    {
        constexpr int rows   = S - 2 * a;      // 80 / 64
        constexpr int cols   = S - 2 * h;      // 88 / 80
        constexpr int strips = rows / 8;       // 10 / 8
        constexpr int nw     = 8 + 4 * d;      // 16 / 24
        for (int idx = threadIdx.x; idx < strips * cols; idx += NTHR) {
            int x  = idx % cols;
            int t  = idx / cols;
            int y0 = a + 8 * t;
            int oc = h + x + SHIFT;
            int ob = (y0 - 2 * d) * SP + oc;
            float v[nw];
#pragma unroll
            for (int i = 0; i < nw; i++) v[i] = P[ob + i * SP];
#pragma unroll
            for (int i = 0; i < 8; i++) {
                Q[(y0 + i) * SP + oc] = w2 * v[2 * d + i]
                                      + w1 * (v[d + i] + v[3 * d + i])
                                      + w0 * (v[i] + v[4 * d + i]);
            }
        }
    }
    __syncthreads();

    // W-conv (horizontal): Q -> P in place (unless LAST). One own float4 load
    // per 4 outputs; neighbor float4s via warp shuffle (adjacent lanes hold
    // adjacent groups of the same row); edge lanes fall back to direct LDS.
    {
        constexpr int n2 = S - 2 * a;                  // 80 / 64
        constexpr int xg = n2 / 4;                     // 20 / 16
        const int lane = threadIdx.x & 31;
        for (int idx = threadIdx.x; idx < n2 * xg; idx += NTHR) {
            int g  = idx % xg;
            int y  = a + idx / xg;
            int x0 = a + 4 * g;                  // logical
            int qc = y * SP + x0 + SHIFT;        // own f4, 16B-aligned
            float4 C = *reinterpret_cast<const float4*>(&Q[qc]);
            float c0, c1, c2, c3;
            if constexpr (d == 4) {
                float4 A4 = shfl_up_f4(C, 2);
                float4 E4 = shfl_dn_f4(C, 2);
                if (lane < 2 || g < 2)       A4 = *reinterpret_cast<const float4*>(&Q[qc - 8]);
                if (lane > 29 || g > xg - 3) E4 = *reinterpret_cast<const float4*>(&Q[qc + 8]);
                float4 AE = f4_add(A4, E4);
                float4 B4 = shfl_up_f4(C, 1);
                float4 D4 = shfl_dn_f4(C, 1);
                if (lane < 1 || g < 1)       B4 = *reinterpret_cast<const float4*>(&Q[qc - 4]);
                if (lane > 30 || g > xg - 2) D4 = *reinterpret_cast<const float4*>(&Q[qc + 4]);
                float4 BD = f4_add(B4, D4);
                c0 = w0 * AE.x + w1 * BD.x + w2 * C.x;
                c1 = w0 * AE.y + w1 * BD.y + w2 * C.y;
                c2 = w0 * AE.z + w1 * BD.z + w2 * C.z;
                c3 = w0 * AE.w + w1 * BD.w + w2 * C.w;
            } else {
                // d == 2: window v[12] = {B4, C, D4}, taps at -4,-2,0,+2,+4
                float4 B4 = shfl_up_f4(C, 1);
                float4 D4 = shfl_dn_f4(C, 1);
                if (lane < 1 || g < 1)       B4 = *reinterpret_cast<const float4*>(&Q[qc - 4]);
                if (lane > 30 || g > xg - 2) D4 = *reinterpret_cast<const float4*>(&Q[qc + 4]);
                float v[12];
                v[0]=B4.x; v[1]=B4.y; v[2]=B4.z; v[3]=B4.w;
                v[4]=C.x;  v[5]=C.y;  v[6]=C.z;  v[7]=C.w;
                v[8]=D4.x; v[9]=D4.y; v[10]=D4.z; v[11]=D4.w;
                c0 = w0*(v[0]+v[8])  + w1*(v[2]+v[6])  + w2*v[4];
                c1 = w0*(v[1]+v[9])  + w1*(v[3]+v[7])  + w2*v[5];
                c2 = w0*(v[2]+v[10]) + w1*(v[4]+v[8])  + w2*v[6];
                c3 = w0*(v[3]+v[11]) + w1*(v[5]+v[9])  + w2*v[7];
            }
            int op = y * SP + x0 + SHIFT;
            bool center = (a == HL) ||
                          (y >= HL && y < S - HL && x0 >= HL && x0 < S - HL);
            if (center) {
                float4 prev = *reinterpret_cast<const float4*>(&P[op]);
                int gy = ty0 + y - HL;
                int gx = tx0 + x0 - HL;
                *reinterpret_cast<float4*>(&wch[gy * IMG + gx]) =
                    make_float4(prev.x - c0, prev.y - c1, prev.z - c2, prev.w - c3);
                if constexpr (LAST)
                    *reinterpret_cast<float4*>(&cch[gy * IMG + gx]) =
                        make_float4(c0, c1, c2, c3);
            }
            if constexpr (!LAST)
                *reinterpret_cast<float4*>(&P[op]) = make_float4(c0, c1, c2, c3);
        }
    }
}

__global__ void __launch_bounds__(NTHR, 3) uwt_kernel(const float* __restrict__ x,
                                                      float* __restrict__ out) {
    extern __shared__ float smem[];
    float* P = smem;
    float* Q = smem + S * SP + 4;

    const int b   = blockIdx.z;
    const int ty0 = blockIdx.y * TS;
    const int tx0 = blockIdx.x * TS;
    const float* xb = x + (size_t)b * IMG * IMG;
    float* ob = out + (size_t)b * 4 * IMG * IMG;

    // ---- level 1: H from gmem, W with gmem prev ----
    const bool interior = (tx0 >= 64 && tx0 <= IMG - TS - 16) &&
                          (ty0 >= 64 && ty0 <= IMG - TS - 16);
    if (interior) h1_pass<false>(xb, Q, ty0, tx0);
    else          h1_pass<true>(xb, Q, ty0, tx0);
    __syncthreads();
    w1_pass(P, Q, xb, ob + 0 * IMG * IMG, ty0, tx0);
    __syncthreads();

    // ---- levels 2, 3 ----
    do_level<2, 2, 6, false>(P, Q, ob + 1 * IMG * IMG, nullptr, ty0, tx0);
    __syncthreads();
    do_level<4, 6, 14, true>(P, Q, ob + 2 * IMG * IMG, ob + 3 * IMG * IMG,
                             ty0, tx0);
}

extern "C" void kernel_launch(void* const* d_in, const int* in_sizes, int n_in,
                              void* d_out, int out_size) {
    const float* x = (const float*)d_in[0];
    float* out     = (float*)d_out;

    cudaFuncSetAttribute(uwt_kernel, cudaFuncAttributeMaxDynamicSharedMemorySize,
                         (int)SMEM_BYTES);

    dim3 grid(IMG / TS, IMG / TS, 8);
    uwt_kernel<<<grid, NTHR, SMEM_BYTES>>>(x, out);
}